// round 13
// baseline (speedup 1.0000x reference)
#include <cuda_runtime.h>

#define BB 2
#define TT 50
#define UU 64
#define PP 5111
#define D4 256   // 4U
#define D2 128   // 2U
#define JJ 50    // MLP hidden
#define JP 64    // padded j-stride
#define NCH 4    // s-chunks in k_main

// k_pre role layout: zin (grouped) + cosX prefetch  (NO xw1 here —
// xw1+prefetch in one launch measured 25us three times; poison pair)
#define NZIN 100                   // 25 bt-groups x 4 d-chunks
#define BID_PF NZIN                // 100..199
#define NPF 100                    // one cosX row per block
#define NBLK_PRE (NZIN + NPF)      // 200

// k_mid role layout (R10-proven): lstm + xw1
#define NXW 160
#define NBLK_MID (2 + NXW)         // 162

#define XP  36               // padded p-stride in transposed x tile
#define NLD 20               // ceil(5111/256)

// ---- scratch (device globals; no allocation allowed) ----
__device__ float g_zin[BB * TT * D4];    // xt@Wk + bl
__device__ float g_G  [BB * TT * JP];    // ht @ W1[:64], padded, zeros j>=50
__device__ float g_xw1[(PP + 32) * JP];  // X @ W1[64:192] + b1, padded
__device__ float g_sink[NPF * 256];      // prefetch sink (deterministic)

typedef unsigned long long ull;

__device__ __forceinline__ float fast_tanh(float x) {
    float r;
    asm("tanh.approx.f32 %0, %1;" : "=f"(r) : "f"(x));
    return r;
}
__device__ __forceinline__ float fast_sigmoid(float x) {
    return fmaf(fast_tanh(0.5f * x), 0.5f, 0.5f);
}
__device__ __forceinline__ ull pk2(float lo, float hi) {
    ull r; asm("mov.b64 %0, {%1, %2};" : "=l"(r) : "f"(lo), "f"(hi)); return r;
}
__device__ __forceinline__ void upk2(float& lo, float& hi, ull v) {
    asm("mov.b64 {%0, %1}, %2;" : "=f"(lo), "=f"(hi) : "l"(v));
}
__device__ __forceinline__ ull fma2(ull a, ull b, ull c) {
    ull d; asm("fma.rn.f32x2 %0, %1, %2, %3;" : "=l"(d) : "l"(a), "l"(b), "l"(c)); return d;
}

// ============================================================
// k_pre: zin (grouped x4 Wk-reuse) + cosX prefetch.
//   bid [0,100)   : zin, group = bid>>2 (4 bt), d-chunk = bid&3;
//                   MLP-16 Wk loads shared by 4 bt.
//   bid [100,200) : cosX L2 prefetch, 1 row per block, MLP-20
//                   (scalar — PP odd, rows not 16B-aligned)
// ============================================================
__global__ void __launch_bounds__(256)
k_pre(const int* __restrict__ tgt, const int* __restrict__ cor,
      const float* __restrict__ X, const float* __restrict__ emb2,
      const float* __restrict__ Wk, const float* __restrict__ bl,
      const float* __restrict__ cosX)
{
    __shared__ float sbuf[1792];   // xs[1024] + zp[768]
    int tid = threadIdx.x;
    int bid = blockIdx.x;

    if (bid < NZIN) {
        // ---------------- zin role (4 bt per block) ----------------
        float* xs = sbuf;            // [4][D4] = 1024
        float* zp = sbuf + 1024;     // [4bt][3ks][64] partials (ks 1..3)
        int g   = bid >> 2;          // bt group 0..24
        int dch = bid & 3;
        int dl  = tid & 63;
        int ks  = tid >> 6;          // 0..3 k-split
        int d   = dch * 64 + dl;
        int bt0 = g * 4;

        for (int i = tid; i < 4 * D4; i += 256) {
            int bl_ = i >> 8;
            int k   = i & (D4 - 1);
            int bt  = bt0 + bl_;
            xs[i] = X[tgt[bt] * D2 + (k & (D2 - 1))] * emb2[cor[bt] * D4 + k];
        }
        __syncthreads();

        int k0 = ks * 64;
        float a0 = 0.f, a1 = 0.f, a2 = 0.f, a3 = 0.f;
        #pragma unroll
        for (int kk = 0; kk < 64; kk += 16) {
            float w[16];
            #pragma unroll
            for (int i = 0; i < 16; i++)
                w[i] = Wk[(k0 + kk + i) * D4 + d];   // 16 LDG in flight
            #pragma unroll
            for (int i = 0; i < 16; i++) {
                int k = k0 + kk + i;
                a0 += xs[k]           * w[i];
                a1 += xs[D4 + k]      * w[i];
                a2 += xs[2 * D4 + k]  * w[i];
                a3 += xs[3 * D4 + k]  * w[i];
            }
        }
        if (ks != 0) {
            int base = (ks - 1) * 64 + dl;
            zp[base]       = a0;
            zp[192 + base] = a1;
            zp[384 + base] = a2;
            zp[576 + base] = a3;
        }
        __syncthreads();
        if (ks == 0) {
            float bv = bl[d];
            g_zin[(bt0 + 0) * D4 + d] = a0 + zp[dl]       + zp[64 + dl]  + zp[128 + dl] + bv;
            g_zin[(bt0 + 1) * D4 + d] = a1 + zp[192 + dl] + zp[256 + dl] + zp[320 + dl] + bv;
            g_zin[(bt0 + 2) * D4 + d] = a2 + zp[384 + dl] + zp[448 + dl] + zp[512 + dl] + bv;
            g_zin[(bt0 + 3) * D4 + d] = a3 + zp[576 + dl] + zp[640 + dl] + zp[704 + dl] + bv;
        }
    } else {
        // ---------------- cosX L2 prefetch: 1 row, MLP-20 scalar ----------
        int pb = bid - BID_PF;               // 0..99
        const float* row = cosX + (size_t)tgt[pb] * PP;
        float v[NLD];
        #pragma unroll
        for (int i = 0; i < NLD; i++) {
            int idx = tid + i * 256;
            v[i] = (idx < PP) ? __ldg(row + idx) : 0.f;
        }
        float s = 0.f;
        #pragma unroll
        for (int i = 0; i < NLD; i++) s += v[i];
        g_sink[pb * 256 + tid] = s;          // deterministic, prevents DCE
    }
}

// ============================================================
// k_mid: LSTM (blocks 0-1, FFMA2 dot) + XW1 GEMM (2..161).
// R10-proven pairing; xw1 hides under the serial LSTM.
// ============================================================
__global__ void __launch_bounds__(256)
k_mid(const float* __restrict__ X,  const float* __restrict__ Wr,
      const float* __restrict__ W1, const float* __restrict__ b1)
{
    __shared__ float sbuf[6720];   // lstm: 6720 floats; xw1 uses 4608
    int tid = threadIdx.x;
    int bid = blockIdx.x;

    if (bid < 2) {
        // ---------------- LSTM role (FFMA2 dot) ----------------
        int b = bid;
        int d = tid;                        // 0..255

        ull wrp[UU / 2];
        #pragma unroll
        for (int i = 0; i < UU / 2; i++)
            wrp[i] = pk2(Wr[(2 * i) * D4 + d], Wr[(2 * i + 1) * D4 + d]);

        float* hts = sbuf;                   // [(TT+1)*UU] = 3264
        float* zs  = sbuf + (TT + 1) * UU;   // [D4]
        float* w1s = zs + D4;                // [UU*JJ] = 3200

        for (int i = tid; i < UU * JJ; i += 256) w1s[i] = W1[i];

        float creg = 0.f;
        if (d < UU) hts[d] = 0.f;

        float znext = g_zin[(b * TT) * D4 + d];
        __syncthreads();

        const ull z2 = pk2(0.f, 0.f);

        for (int t = 0; t < TT; t++) {
            float z = znext;
            if (t < TT - 1)
                znext = g_zin[(b * TT + t + 1) * D4 + d];

            const ull* h2 = (const ull*)(hts + t * UU);
            ull a0 = z2, a1 = z2, a2 = z2, a3 = z2;
            #pragma unroll
            for (int i = 0; i < UU / 2; i += 4) {
                a0 = fma2(h2[i],     wrp[i],     a0);
                a1 = fma2(h2[i + 1], wrp[i + 1], a1);
                a2 = fma2(h2[i + 2], wrp[i + 2], a2);
                a3 = fma2(h2[i + 3], wrp[i + 3], a3);
            }
            float f0, f1, f2, f3, f4, f5, f6, f7;
            upk2(f0, f1, a0); upk2(f2, f3, a1);
            upk2(f4, f5, a2); upk2(f6, f7, a3);
            zs[d] = z + ((f0 + f1) + (f2 + f3)) + ((f4 + f5) + (f6 + f7));
            __syncthreads();
            if (d < UU) {
                float gi = fast_sigmoid(zs[d]);
                float gf = fast_sigmoid(zs[UU + d]);
                float gg = fast_tanh(zs[2 * UU + d]);
                float go = fast_sigmoid(zs[3 * UU + d]);
                creg = gf * creg + gi * gg;
                hts[(t + 1) * UU + d] = go * fast_tanh(creg);
            }
            __syncthreads();
        }

        // fused: G[b,t,j] = sum_u h_t[u]*W1[u,j]; padded stride JP
        for (int idx = tid; idx < TT * JP; idx += 256) {
            int t = idx >> 6;
            int j = idx & (JP - 1);
            float v = 0.f;
            if (j < JJ) {
                const float* h = hts + (t + 1) * UU;
                float s0 = 0.f, s1 = 0.f;
                #pragma unroll
                for (int u = 0; u < UU; u += 2) {
                    s0 += h[u]     * w1s[u * JJ + j];
                    s1 += h[u + 1] * w1s[(u + 1) * JJ + j];
                }
                v = s0 + s1;
            }
            g_G[(b * TT + t) * JP + j] = v;
        }
    } else {
        // ---------------- XW1 role ----------------
        float* xsmT = sbuf;                  // [D2][XP] = 4608
        int p0 = (bid - 2) * 32;
        for (int i = tid; i < 32 * D2; i += 256) {
            int pl = i >> 7;
            int k  = i & (D2 - 1);
            int p  = p0 + pl;
            xsmT[k * XP + pl] = (p < PP) ? X[p * D2 + k] : 0.f;
        }
        __syncthreads();

        int w = tid >> 5;
        int l = tid & 31;
        int j1 = l + 32;
        bool v1 = (j1 < JJ);
        int pq = w * 4;
        const float* W1b = W1 + UU * JJ;

        float acc[4][2];
        float b0 = b1[l];
        float b1v = v1 ? b1[j1] : 0.f;
        #pragma unroll
        for (int m = 0; m < 4; m++) { acc[m][0] = b0; acc[m][1] = b1v; }

        #pragma unroll 4
        for (int k = 0; k < D2; k++) {
            float4 xv = *(const float4*)(xsmT + k * XP + pq);
            float wv0 = __ldg(W1b + k * JJ + l);
            float wv1 = v1 ? __ldg(W1b + k * JJ + j1) : 0.f;
            acc[0][0] += xv.x * wv0;  acc[0][1] += xv.x * wv1;
            acc[1][0] += xv.y * wv0;  acc[1][1] += xv.y * wv1;
            acc[2][0] += xv.z * wv0;  acc[2][1] += xv.z * wv1;
            acc[3][0] += xv.w * wv0;  acc[3][1] += xv.w * wv1;
        }

        #pragma unroll
        for (int m = 0; m < 4; m++) {
            int p = p0 + pq + m;
            if (p < PP) {
                g_xw1[p * JP + l] = acc[m][0];
                g_xw1[p * JP + j1] = v1 ? acc[m][1] : 0.f;
            }
        }
    }
}

// ============================================================
// k_main: 8 threads per (b,p); member q owns j in [8q,8q+8).
// grid = (160 p-blocks, NCH=4 s-chunks, 2 b) = 1280 blocks.
// smem a-pregather -> zero-LDG inner loop; light iters are cheap
// (1 LDS + 4 FFMA2), so extra chunks now pay off in occupancy.
// __launch_bounds__(256,6) caps regs for ~48 warps/SM residency.
// ============================================================
__global__ void __launch_bounds__(256, 6)
k_main(const int* __restrict__ tgt, const float* __restrict__ cosX,
       const float* __restrict__ W2, const float* __restrict__ b2,
       float* __restrict__ out)
{
    __shared__ float Gs[TT * JP];    // 12.8 KB
    __shared__ float As[TT * 32];    // 6.4 KB: a[t][p_local]
    __shared__ int   tg[TT];
    int tid = threadIdx.x;
    int b = blockIdx.z;
    int p0 = blockIdx.x * 32;

    if (tid < TT) tg[tid] = tgt[b * TT + tid];
    __syncthreads();

    {
        const float4* src = (const float4*)(g_G + b * TT * JP);
        float4* dst = (float4*)Gs;
        for (int i = tid; i < TT * JP / 4; i += 256) dst[i] = src[i];
        for (int idx = tid; idx < TT * 32; idx += 256) {
            int t  = idx >> 5;
            int p  = p0 + (idx & 31);
            As[idx] = (p < PP) ? __ldg(cosX + (size_t)tg[t] * PP + p) : 0.f;
        }
    }
    __syncthreads();

    int pl = tid >> 3;               // 0..31
    int p  = p0 + pl;
    int q  = tid & 7;
    int jb = q * 8;
    int ch = blockIdx.y;
    const int s_lo = (ch * TT) / NCH;             // 0,12,25,37
    const int s_hi = ((ch + 1) * TT) / NCH - 1;   // 11,24,36,49
    bool valid = (p < PP);

    ull ac0, ac1, ac2, ac3;
    {
        const ulonglong2* x2 = (const ulonglong2*)(g_xw1 + p * JP + jb);
        ulonglong2 xa = x2[0], xb = x2[1];
        ac0 = xa.x; ac1 = xa.y; ac2 = xb.x; ac3 = xb.y;
    }
    float w2r[8];
    #pragma unroll
    for (int m = 0; m < 8; m++) {
        int j = jb + m;
        w2r[m] = (j < JJ) ? W2[j] : 0.f;
    }
    float bias2 = b2[0];

    // phase A: light-accumulate t = 49 .. s_hi+1 (no output; cheap: LDS+FFMA2)
    #pragma unroll 4
    for (int t = TT - 1; t > s_hi; t--) {
        float a = As[t * 32 + pl];
        ull ab = pk2(a, a);
        const ulonglong2* g2 = (const ulonglong2*)(Gs + t * JP + jb);
        ulonglong2 ga = g2[0], gb = g2[1];
        ac0 = fma2(ga.x, ab, ac0);
        ac1 = fma2(ga.y, ab, ac1);
        ac2 = fma2(gb.x, ab, ac2);
        ac3 = fma2(gb.y, ab, ac3);
    }

    // phase B: s = s_hi .. s_lo with output
    #pragma unroll 4
    for (int s = s_hi; s >= s_lo; s--) {
        float a = As[s * 32 + pl];
        ull ab = pk2(a, a);
        const ulonglong2* g2 = (const ulonglong2*)(Gs + s * JP + jb);
        ulonglong2 ga = g2[0], gb = g2[1];
        ac0 = fma2(ga.x, ab, ac0);
        ac1 = fma2(ga.y, ab, ac1);
        ac2 = fma2(gb.x, ab, ac2);
        ac3 = fma2(gb.y, ab, ac3);

        float f0, f1, f2, f3, f4, f5, f6, f7;
        upk2(f0, f1, ac0); upk2(f2, f3, ac1);
        upk2(f4, f5, ac2); upk2(f6, f7, ac3);

        float part = fmaxf(f0, 0.f) * w2r[0];
        part = fmaf(fmaxf(f1, 0.f), w2r[1], part);
        part = fmaf(fmaxf(f2, 0.f), w2r[2], part);
        part = fmaf(fmaxf(f3, 0.f), w2r[3], part);
        part = fmaf(fmaxf(f4, 0.f), w2r[4], part);
        part = fmaf(fmaxf(f5, 0.f), w2r[5], part);
        part = fmaf(fmaxf(f6, 0.f), w2r[6], part);
        part = fmaf(fmaxf(f7, 0.f), w2r[7], part);

        part += __shfl_xor_sync(0xffffffffu, part, 1);
        part += __shfl_xor_sync(0xffffffffu, part, 2);
        part += __shfl_xor_sync(0xffffffffu, part, 4);
        if (q == 0 && valid)
            out[(b * TT + s) * PP + p] = part + bias2;
    }
}

// ============================================================
// Launcher
// ============================================================
extern "C" void kernel_launch(void* const* d_in, const int* in_sizes, int n_in,
                              void* d_out, int out_size)
{
    const int   *tgt = nullptr, *cor = nullptr;
    const float *X = nullptr, *cosX = nullptr, *emb2 = nullptr, *Wk = nullptr;
    const float *Wr = nullptr, *bl = nullptr, *W1 = nullptr, *b1 = nullptr;
    const float *W2 = nullptr, *b2 = nullptr;

    int cnt1 = 0;
    for (int i = 0; i < n_in; i++) if (in_sizes[i] == 1) cnt1++;
    int seen1 = 0;

    for (int i = 0; i < n_in; i++) {
        int sz = in_sizes[i];
        const void* ptr = d_in[i];
        if (sz == BB * TT) {
            if (!tgt) tgt = (const int*)ptr; else cor = (const int*)ptr;
        } else if (sz == PP * PP)   cosX = (const float*)ptr;
        else if (sz == PP * D2)     X    = (const float*)ptr;
        else if (sz == D4 * D4)     Wk   = (const float*)ptr;
        else if (sz == UU * D4)     Wr   = (const float*)ptr;
        else if (sz == 2 * D4)      emb2 = (const float*)ptr;
        else if (sz == D4)          bl   = (const float*)ptr;
        else if (sz == 3 * UU * JJ) W1   = (const float*)ptr;
        else if (sz == JJ) {
            if (!b1) b1 = (const float*)ptr; else W2 = (const float*)ptr;
        } else if (sz == 1) {
            seen1++;
            if (seen1 == cnt1) b2 = (const float*)ptr;
        }
    }

    // 1) zin (grouped, Wk reuse x4) + cosX prefetch (R10 pairing)
    k_pre<<<NBLK_PRE, 256>>>(tgt, cor, X, emb2, Wk, bl, cosX);
    // 2) LSTM (FFMA2) + XW1 GEMM (R10-proven pairing)
    k_mid<<<NBLK_MID, 256>>>(X, Wr, W1, b1);
    // 3) suffix-sum + MLP; 4 s-chunks now that light iters are LDS-cheap
    k_main<<<dim3(160, NCH, 2), 256>>>(tgt, cosX, W2, b2, (float*)d_out);
}

// round 14
// speedup vs baseline: 1.1850x; 1.1850x over previous
#include <cuda_runtime.h>

#define BB 2
#define TT 50
#define UU 64
#define PP 5111
#define D4 256   // 4U
#define D2 128   // 2U
#define JJ 50    // MLP hidden
#define JP 64    // padded j-stride
#define SCH 25   // s per chunk (2 chunks)

// k_pre role layout (R10-proven): zin 400 blocks + prefetch 100
#define NZIN 400                   // 100 bt x 4 d-chunks
#define BID_PF NZIN                // 400..499
#define NPF 100                    // one cosX row per block
#define NBLK_PRE (NZIN + NPF)      // 500

// k_mid role layout (R10-proven): lstm + xw1
#define NXW 160
#define NBLK_MID (2 + NXW)         // 162

#define XP  36               // padded p-stride in transposed x tile
#define NLD 20               // ceil(5111/256)

// ---- scratch (device globals; no allocation allowed) ----
__device__ float g_zin[BB * TT * D4];    // xt@Wk + bl
__device__ float g_G  [BB * TT * JP];    // ht @ W1[:64], padded, zeros j>=50
__device__ float g_xw1[(PP + 64) * JP];  // X @ W1[64:192] + b1, padded
__device__ float g_sink[NPF * 256];      // prefetch sink (deterministic)

typedef unsigned long long ull;

__device__ __forceinline__ float fast_tanh(float x) {
    float r;
    asm("tanh.approx.f32 %0, %1;" : "=f"(r) : "f"(x));
    return r;
}
__device__ __forceinline__ float fast_sigmoid(float x) {
    return fmaf(fast_tanh(0.5f * x), 0.5f, 0.5f);
}
__device__ __forceinline__ ull pk2(float lo, float hi) {
    ull r; asm("mov.b64 %0, {%1, %2};" : "=l"(r) : "f"(lo), "f"(hi)); return r;
}
__device__ __forceinline__ void upk2(float& lo, float& hi, ull v) {
    asm("mov.b64 {%0, %1}, %2;" : "=f"(lo), "=f"(hi) : "l"(v));
}
__device__ __forceinline__ ull fma2(ull a, ull b, ull c) {
    ull d; asm("fma.rn.f32x2 %0, %1, %2, %3;" : "=l"(d) : "l"(a), "l"(b), "l"(c)); return d;
}

// ============================================================
// k_pre (EXACT R10): zin + cosX prefetch.
//   bid [0,400)   : zin (bt = bid>>2, d-chunk = bid&3), MLP-16
//   bid [400,500) : cosX L2 prefetch, 1 row per block, MLP-20
//                   (scalar — PP odd, rows not 16B-aligned)
// ============================================================
__global__ void __launch_bounds__(256)
k_pre(const int* __restrict__ tgt, const int* __restrict__ cor,
      const float* __restrict__ X, const float* __restrict__ emb2,
      const float* __restrict__ Wk, const float* __restrict__ bl,
      const float* __restrict__ cosX)
{
    __shared__ float sbuf[512];    // zin: xs[256] + zp[256]
    int tid = threadIdx.x;
    int bid = blockIdx.x;

    if (bid < NZIN) {
        float* xs = sbuf;            // [D4]
        float* zp = sbuf + D4;       // partials (ks 1..3)
        int bt = bid >> 2;
        int ch = bid & 3;
        int dl = tid & 63;
        int ks = tid >> 6;           // 0..3 k-split
        int d  = ch * 64 + dl;

        {
            int tg = tgt[bt];
            int cr = cor[bt];
            xs[tid] = X[tg * D2 + (tid & (D2 - 1))] * emb2[cr * D4 + tid];
        }
        __syncthreads();

        int k0 = ks * 64;
        float acc = 0.f;
        #pragma unroll
        for (int kk = 0; kk < 64; kk += 16) {
            float w[16];
            #pragma unroll
            for (int i = 0; i < 16; i++)
                w[i] = Wk[(k0 + kk + i) * D4 + d];   // 16 LDG in flight
            #pragma unroll
            for (int i = 0; i < 16; i++)
                acc += xs[k0 + kk + i] * w[i];
        }
        if (ks != 0) zp[ks * 64 + dl] = acc;
        __syncthreads();
        if (ks == 0)
            g_zin[bt * D4 + d] = acc + zp[64 + dl] + zp[128 + dl] + zp[192 + dl] + bl[d];
    } else {
        int pb = bid - BID_PF;               // 0..99
        const float* row = cosX + (size_t)tgt[pb] * PP;
        float v[NLD];
        #pragma unroll
        for (int i = 0; i < NLD; i++) {
            int idx = tid + i * 256;
            v[i] = (idx < PP) ? __ldg(row + idx) : 0.f;   // MLP = 20
        }
        float s = 0.f;
        #pragma unroll
        for (int i = 0; i < NLD; i++) s += v[i];
        g_sink[pb * 256 + tid] = s;          // deterministic, prevents DCE
    }
}

// ============================================================
// k_mid (EXACT R10): LSTM (blocks 0-1, FFMA2) + XW1 (2..161).
// ============================================================
__global__ void __launch_bounds__(256)
k_mid(const float* __restrict__ X,  const float* __restrict__ Wr,
      const float* __restrict__ W1, const float* __restrict__ b1)
{
    __shared__ float sbuf[6720];   // lstm: 6720 floats; xw1 uses 4608
    int tid = threadIdx.x;
    int bid = blockIdx.x;

    if (bid < 2) {
        // ---------------- LSTM role (FFMA2 dot) ----------------
        int b = bid;
        int d = tid;                        // 0..255

        ull wrp[UU / 2];
        #pragma unroll
        for (int i = 0; i < UU / 2; i++)
            wrp[i] = pk2(Wr[(2 * i) * D4 + d], Wr[(2 * i + 1) * D4 + d]);

        float* hts = sbuf;                   // [(TT+1)*UU] = 3264
        float* zs  = sbuf + (TT + 1) * UU;   // [D4]
        float* w1s = zs + D4;                // [UU*JJ] = 3200

        for (int i = tid; i < UU * JJ; i += 256) w1s[i] = W1[i];

        float creg = 0.f;
        if (d < UU) hts[d] = 0.f;

        float znext = g_zin[(b * TT) * D4 + d];
        __syncthreads();

        const ull z2 = pk2(0.f, 0.f);

        for (int t = 0; t < TT; t++) {
            float z = znext;
            if (t < TT - 1)
                znext = g_zin[(b * TT + t + 1) * D4 + d];

            const ull* h2 = (const ull*)(hts + t * UU);
            ull a0 = z2, a1 = z2, a2 = z2, a3 = z2;
            #pragma unroll
            for (int i = 0; i < UU / 2; i += 4) {
                a0 = fma2(h2[i],     wrp[i],     a0);
                a1 = fma2(h2[i + 1], wrp[i + 1], a1);
                a2 = fma2(h2[i + 2], wrp[i + 2], a2);
                a3 = fma2(h2[i + 3], wrp[i + 3], a3);
            }
            float f0, f1, f2, f3, f4, f5, f6, f7;
            upk2(f0, f1, a0); upk2(f2, f3, a1);
            upk2(f4, f5, a2); upk2(f6, f7, a3);
            zs[d] = z + ((f0 + f1) + (f2 + f3)) + ((f4 + f5) + (f6 + f7));
            __syncthreads();
            if (d < UU) {
                float gi = fast_sigmoid(zs[d]);
                float gf = fast_sigmoid(zs[UU + d]);
                float gg = fast_tanh(zs[2 * UU + d]);
                float go = fast_sigmoid(zs[3 * UU + d]);
                creg = gf * creg + gi * gg;
                hts[(t + 1) * UU + d] = go * fast_tanh(creg);
            }
            __syncthreads();
        }

        // fused: G[b,t,j] = sum_u h_t[u]*W1[u,j]; padded stride JP
        for (int idx = tid; idx < TT * JP; idx += 256) {
            int t = idx >> 6;
            int j = idx & (JP - 1);
            float v = 0.f;
            if (j < JJ) {
                const float* h = hts + (t + 1) * UU;
                float s0 = 0.f, s1 = 0.f;
                #pragma unroll
                for (int u = 0; u < UU; u += 2) {
                    s0 += h[u]     * w1s[u * JJ + j];
                    s1 += h[u + 1] * w1s[(u + 1) * JJ + j];
                }
                v = s0 + s1;
            }
            g_G[(b * TT + t) * JP + j] = v;
        }
    } else {
        // ---------------- XW1 role ----------------
        float* xsmT = sbuf;                  // [D2][XP] = 4608
        int p0 = (bid - 2) * 32;
        for (int i = tid; i < 32 * D2; i += 256) {
            int pl = i >> 7;
            int k  = i & (D2 - 1);
            int p  = p0 + pl;
            xsmT[k * XP + pl] = (p < PP) ? X[p * D2 + k] : 0.f;
        }
        __syncthreads();

        int w = tid >> 5;
        int l = tid & 31;
        int j1 = l + 32;
        bool v1 = (j1 < JJ);
        int pq = w * 4;
        const float* W1b = W1 + UU * JJ;

        float acc[4][2];
        float b0 = b1[l];
        float b1v = v1 ? b1[j1] : 0.f;
        #pragma unroll
        for (int m = 0; m < 4; m++) { acc[m][0] = b0; acc[m][1] = b1v; }

        #pragma unroll 4
        for (int k = 0; k < D2; k++) {
            float4 xv = *(const float4*)(xsmT + k * XP + pq);
            float wv0 = __ldg(W1b + k * JJ + l);
            float wv1 = v1 ? __ldg(W1b + k * JJ + j1) : 0.f;
            acc[0][0] += xv.x * wv0;  acc[0][1] += xv.x * wv1;
            acc[1][0] += xv.y * wv0;  acc[1][1] += xv.y * wv1;
            acc[2][0] += xv.z * wv0;  acc[2][1] += xv.z * wv1;
            acc[3][0] += xv.w * wv0;  acc[3][1] += xv.w * wv1;
        }

        #pragma unroll
        for (int m = 0; m < 4; m++) {
            int p = p0 + pq + m;
            if (p < PP) {
                g_xw1[p * JP + l] = acc[m][0];
                g_xw1[p * JP + j1] = v1 ? acc[m][1] : 0.f;
            }
        }
    }
}

// ============================================================
// k_main (NEW): 4 threads per (b,p); member q owns j in [16q,16q+16).
// Block covers 64 p. grid = (80 p-blocks, 2 s-chunks, 2 b).
// One a-broadcast + one reduce tree serve 16 j (was 8); SHFL 3->2;
// per-thread ILP: 4 indep LDS.128 + 8 indep FFMA2 per iter.
// ============================================================
__global__ void __launch_bounds__(256)
k_main(const int* __restrict__ tgt, const float* __restrict__ cosX,
       const float* __restrict__ W2, const float* __restrict__ b2,
       float* __restrict__ out)
{
    __shared__ float Gs[TT * JP];    // 12.8 KB
    __shared__ float As[TT * 64];    // 12.8 KB: a[t][p_local]
    __shared__ int   tg[TT];
    int tid = threadIdx.x;
    int b = blockIdx.z;
    int p0 = blockIdx.x * 64;

    if (tid < TT) tg[tid] = tgt[b * TT + tid];
    __syncthreads();

    {
        const float4* src = (const float4*)(g_G + b * TT * JP);
        float4* dst = (float4*)Gs;
        for (int i = tid; i < TT * JP / 4; i += 256) dst[i] = src[i];
        // pre-gather a: coalesced 64-wide rows, 3200 loads in flight
        for (int idx = tid; idx < TT * 64; idx += 256) {
            int t = idx >> 6;
            int p = p0 + (idx & 63);
            As[idx] = (p < PP) ? __ldg(cosX + (size_t)tg[t] * PP + p) : 0.f;
        }
    }
    __syncthreads();

    int pl = tid >> 2;               // 0..63
    int p  = p0 + pl;
    int q  = tid & 3;
    int jb = q * 16;
    int ch = blockIdx.y;
    const int s_lo = ch * SCH;
    const int s_hi = s_lo + SCH - 1;
    bool valid = (p < PP);

    // 8 packed accumulators = 16 j, initialized from XW1 row
    ull ac[8];
    {
        const ulonglong2* x2 = (const ulonglong2*)(g_xw1 + p * JP + jb);
        #pragma unroll
        for (int i = 0; i < 4; i++) {
            ulonglong2 xa = x2[i];
            ac[2 * i] = xa.x; ac[2 * i + 1] = xa.y;
        }
    }
    float w2r[16];
    #pragma unroll
    for (int m = 0; m < 16; m++) {
        int j = jb + m;
        w2r[m] = (j < JJ) ? W2[j] : 0.f;
    }
    float bias2 = b2[0];

    // phase A (chunk 0 only): accumulate tail t = 49..25, no output
    if (ch == 0) {
        #pragma unroll 5
        for (int t = TT - 1; t > s_hi; t--) {
            float a = As[t * 64 + pl];
            ull ab = pk2(a, a);
            const ulonglong2* g2 = (const ulonglong2*)(Gs + t * JP + jb);
            #pragma unroll
            for (int i = 0; i < 4; i++) {
                ulonglong2 ga = g2[i];
                ac[2 * i]     = fma2(ga.x, ab, ac[2 * i]);
                ac[2 * i + 1] = fma2(ga.y, ab, ac[2 * i + 1]);
            }
        }
    }

    // phase B: s = s_hi .. s_lo with output
    #pragma unroll 5
    for (int s = s_hi; s >= s_lo; s--) {
        float a = As[s * 64 + pl];
        ull ab = pk2(a, a);
        const ulonglong2* g2 = (const ulonglong2*)(Gs + s * JP + jb);
        #pragma unroll
        for (int i = 0; i < 4; i++) {
            ulonglong2 ga = g2[i];
            ac[2 * i]     = fma2(ga.x, ab, ac[2 * i]);
            ac[2 * i + 1] = fma2(ga.y, ab, ac[2 * i + 1]);
        }

        float part = 0.f;
        #pragma unroll
        for (int i = 0; i < 8; i++) {
            float lo, hi;
            upk2(lo, hi, ac[i]);
            part = fmaf(fmaxf(lo, 0.f), w2r[2 * i],     part);
            part = fmaf(fmaxf(hi, 0.f), w2r[2 * i + 1], part);
        }

        part += __shfl_xor_sync(0xffffffffu, part, 1);
        part += __shfl_xor_sync(0xffffffffu, part, 2);
        if (q == 0 && valid)
            out[(b * TT + s) * PP + p] = part + bias2;
    }
}

// ============================================================
// Launcher
// ============================================================
extern "C" void kernel_launch(void* const* d_in, const int* in_sizes, int n_in,
                              void* d_out, int out_size)
{
    const int   *tgt = nullptr, *cor = nullptr;
    const float *X = nullptr, *cosX = nullptr, *emb2 = nullptr, *Wk = nullptr;
    const float *Wr = nullptr, *bl = nullptr, *W1 = nullptr, *b1 = nullptr;
    const float *W2 = nullptr, *b2 = nullptr;

    int cnt1 = 0;
    for (int i = 0; i < n_in; i++) if (in_sizes[i] == 1) cnt1++;
    int seen1 = 0;

    for (int i = 0; i < n_in; i++) {
        int sz = in_sizes[i];
        const void* ptr = d_in[i];
        if (sz == BB * TT) {
            if (!tgt) tgt = (const int*)ptr; else cor = (const int*)ptr;
        } else if (sz == PP * PP)   cosX = (const float*)ptr;
        else if (sz == PP * D2)     X    = (const float*)ptr;
        else if (sz == D4 * D4)     Wk   = (const float*)ptr;
        else if (sz == UU * D4)     Wr   = (const float*)ptr;
        else if (sz == 2 * D4)      emb2 = (const float*)ptr;
        else if (sz == D4)          bl   = (const float*)ptr;
        else if (sz == 3 * UU * JJ) W1   = (const float*)ptr;
        else if (sz == JJ) {
            if (!b1) b1 = (const float*)ptr; else W2 = (const float*)ptr;
        } else if (sz == 1) {
            seen1++;
            if (seen1 == cnt1) b2 = (const float*)ptr;
        }
    }

    // 1) zin (400 blocks, MLP-16) + cosX prefetch (R10 exact)
    k_pre<<<NBLK_PRE, 256>>>(tgt, cor, X, emb2, Wk, bl, cosX);
    // 2) LSTM (FFMA2) + XW1 GEMM (R10 exact)
    k_mid<<<NBLK_MID, 256>>>(X, Wr, W1, b1);
    // 3) suffix-sum + MLP; 16-j layout, 2-SHFL reduce, 2 s-chunks
    k_main<<<dim3(80, 2, 2), 256>>>(tgt, cosX, W2, b2, (float*)d_out);
}

// round 16
// speedup vs baseline: 1.2616x; 1.0647x over previous
#include <cuda_runtime.h>

#define BB 2
#define TT 50
#define UU 64
#define PP 5111
#define D4 256   // 4U
#define D2 128   // 2U
#define JJ 50    // MLP hidden
#define JP 64    // padded j-stride
#define SCH 25   // s per chunk (2 chunks)

// k_pre role layout (R10-proven): zin 400 blocks + prefetch 100
#define NZIN 400                   // 100 bt x 4 d-chunks
#define BID_PF NZIN                // 400..499
#define NPF 100                    // one cosX row per block
#define NBLK_PRE (NZIN + NPF)      // 500

// k_mid role layout (R10-proven): lstm + xw1
#define NXW 160
#define NBLK_MID (2 + NXW)         // 162

#define XP  36               // padded p-stride in transposed x tile
#define NLD 20               // ceil(5111/256)

// ---- scratch (device globals; no allocation allowed) ----
__device__ float g_zin[BB * TT * D4];    // xt@Wk + bl
__device__ float g_G  [BB * TT * JP];    // ht @ W1[:64], padded, zeros j>=50
__device__ float g_xw1[(PP + 64) * JP];  // X @ W1[64:192] + b1, padded
__device__ float g_sink[NPF * 256];      // prefetch sink (deterministic)

typedef unsigned long long ull;

__device__ __forceinline__ float fast_tanh(float x) {
    float r;
    asm("tanh.approx.f32 %0, %1;" : "=f"(r) : "f"(x));
    return r;
}
__device__ __forceinline__ float fast_sigmoid(float x) {
    return fmaf(fast_tanh(0.5f * x), 0.5f, 0.5f);
}
__device__ __forceinline__ ull pk2(float lo, float hi) {
    ull r; asm("mov.b64 %0, {%1, %2};" : "=l"(r) : "f"(lo), "f"(hi)); return r;
}
__device__ __forceinline__ void upk2(float& lo, float& hi, ull v) {
    asm("mov.b64 {%0, %1}, %2;" : "=f"(lo), "=f"(hi) : "l"(v));
}
__device__ __forceinline__ ull fma2(ull a, ull b, ull c) {
    ull d; asm("fma.rn.f32x2 %0, %1, %2, %3;" : "=l"(d) : "l"(a), "l"(b), "l"(c)); return d;
}

// ============================================================
// k_pre (EXACT R10): zin + cosX prefetch.
//   bid [0,400)   : zin (bt = bid>>2, d-chunk = bid&3), MLP-16
//   bid [400,500) : cosX L2 prefetch, 1 row per block, MLP-20
//                   (scalar — PP odd, rows not 16B-aligned)
// ============================================================
__global__ void __launch_bounds__(256)
k_pre(const int* __restrict__ tgt, const int* __restrict__ cor,
      const float* __restrict__ X, const float* __restrict__ emb2,
      const float* __restrict__ Wk, const float* __restrict__ bl,
      const float* __restrict__ cosX)
{
    __shared__ float sbuf[512];    // zin: xs[256] + zp[256]
    int tid = threadIdx.x;
    int bid = blockIdx.x;

    if (bid < NZIN) {
        float* xs = sbuf;            // [D4]
        float* zp = sbuf + D4;       // partials (ks 1..3)
        int bt = bid >> 2;
        int ch = bid & 3;
        int dl = tid & 63;
        int ks = tid >> 6;           // 0..3 k-split
        int d  = ch * 64 + dl;

        {
            int tg = tgt[bt];
            int cr = cor[bt];
            xs[tid] = X[tg * D2 + (tid & (D2 - 1))] * emb2[cr * D4 + tid];
        }
        __syncthreads();

        int k0 = ks * 64;
        float acc = 0.f;
        #pragma unroll
        for (int kk = 0; kk < 64; kk += 16) {
            float w[16];
            #pragma unroll
            for (int i = 0; i < 16; i++)
                w[i] = Wk[(k0 + kk + i) * D4 + d];   // 16 LDG in flight
            #pragma unroll
            for (int i = 0; i < 16; i++)
                acc += xs[k0 + kk + i] * w[i];
        }
        if (ks != 0) zp[ks * 64 + dl] = acc;
        __syncthreads();
        if (ks == 0)
            g_zin[bt * D4 + d] = acc + zp[64 + dl] + zp[128 + dl] + zp[192 + dl] + bl[d];
    } else {
        int pb = bid - BID_PF;               // 0..99
        const float* row = cosX + (size_t)tgt[pb] * PP;
        float v[NLD];
        #pragma unroll
        for (int i = 0; i < NLD; i++) {
            int idx = tid + i * 256;
            v[i] = (idx < PP) ? __ldg(row + idx) : 0.f;   // MLP = 20
        }
        float s = 0.f;
        #pragma unroll
        for (int i = 0; i < NLD; i++) s += v[i];
        g_sink[pb * 256 + tid] = s;          // deterministic, prevents DCE
    }
}

// ============================================================
// k_mid (EXACT R10): LSTM (blocks 0-1, FFMA2) + XW1 (2..161).
// ============================================================
__global__ void __launch_bounds__(256)
k_mid(const float* __restrict__ X,  const float* __restrict__ Wr,
      const float* __restrict__ W1, const float* __restrict__ b1)
{
    __shared__ float sbuf[6720];   // lstm: 6720 floats; xw1 uses 4608
    int tid = threadIdx.x;
    int bid = blockIdx.x;

    if (bid < 2) {
        // ---------------- LSTM role (FFMA2 dot) ----------------
        int b = bid;
        int d = tid;                        // 0..255

        ull wrp[UU / 2];
        #pragma unroll
        for (int i = 0; i < UU / 2; i++)
            wrp[i] = pk2(Wr[(2 * i) * D4 + d], Wr[(2 * i + 1) * D4 + d]);

        float* hts = sbuf;                   // [(TT+1)*UU] = 3264
        float* zs  = sbuf + (TT + 1) * UU;   // [D4]
        float* w1s = zs + D4;                // [UU*JJ] = 3200

        for (int i = tid; i < UU * JJ; i += 256) w1s[i] = W1[i];

        float creg = 0.f;
        if (d < UU) hts[d] = 0.f;

        float znext = g_zin[(b * TT) * D4 + d];
        __syncthreads();

        const ull z2 = pk2(0.f, 0.f);

        for (int t = 0; t < TT; t++) {
            float z = znext;
            if (t < TT - 1)
                znext = g_zin[(b * TT + t + 1) * D4 + d];

            const ull* h2 = (const ull*)(hts + t * UU);
            ull a0 = z2, a1 = z2, a2 = z2, a3 = z2;
            #pragma unroll
            for (int i = 0; i < UU / 2; i += 4) {
                a0 = fma2(h2[i],     wrp[i],     a0);
                a1 = fma2(h2[i + 1], wrp[i + 1], a1);
                a2 = fma2(h2[i + 2], wrp[i + 2], a2);
                a3 = fma2(h2[i + 3], wrp[i + 3], a3);
            }
            float f0, f1, f2, f3, f4, f5, f6, f7;
            upk2(f0, f1, a0); upk2(f2, f3, a1);
            upk2(f4, f5, a2); upk2(f6, f7, a3);
            zs[d] = z + ((f0 + f1) + (f2 + f3)) + ((f4 + f5) + (f6 + f7));
            __syncthreads();
            if (d < UU) {
                float gi = fast_sigmoid(zs[d]);
                float gf = fast_sigmoid(zs[UU + d]);
                float gg = fast_tanh(zs[2 * UU + d]);
                float go = fast_sigmoid(zs[3 * UU + d]);
                creg = gf * creg + gi * gg;
                hts[(t + 1) * UU + d] = go * fast_tanh(creg);
            }
            __syncthreads();
        }

        // fused: G[b,t,j] = sum_u h_t[u]*W1[u,j]; padded stride JP
        for (int idx = tid; idx < TT * JP; idx += 256) {
            int t = idx >> 6;
            int j = idx & (JP - 1);
            float v = 0.f;
            if (j < JJ) {
                const float* h = hts + (t + 1) * UU;
                float s0 = 0.f, s1 = 0.f;
                #pragma unroll
                for (int u = 0; u < UU; u += 2) {
                    s0 += h[u]     * w1s[u * JJ + j];
                    s1 += h[u + 1] * w1s[(u + 1) * JJ + j];
                }
                v = s0 + s1;
            }
            g_G[(b * TT + t) * JP + j] = v;
        }
    } else {
        // ---------------- XW1 role ----------------
        float* xsmT = sbuf;                  // [D2][XP] = 4608
        int p0 = (bid - 2) * 32;
        for (int i = tid; i < 32 * D2; i += 256) {
            int pl = i >> 7;
            int k  = i & (D2 - 1);
            int p  = p0 + pl;
            xsmT[k * XP + pl] = (p < PP) ? X[p * D2 + k] : 0.f;
        }
        __syncthreads();

        int w = tid >> 5;
        int l = tid & 31;
        int j1 = l + 32;
        bool v1 = (j1 < JJ);
        int pq = w * 4;
        const float* W1b = W1 + UU * JJ;

        float acc[4][2];
        float b0 = b1[l];
        float b1v = v1 ? b1[j1] : 0.f;
        #pragma unroll
        for (int m = 0; m < 4; m++) { acc[m][0] = b0; acc[m][1] = b1v; }

        #pragma unroll 4
        for (int k = 0; k < D2; k++) {
            float4 xv = *(const float4*)(xsmT + k * XP + pq);
            float wv0 = __ldg(W1b + k * JJ + l);
            float wv1 = v1 ? __ldg(W1b + k * JJ + j1) : 0.f;
            acc[0][0] += xv.x * wv0;  acc[0][1] += xv.x * wv1;
            acc[1][0] += xv.y * wv0;  acc[1][1] += xv.y * wv1;
            acc[2][0] += xv.z * wv0;  acc[2][1] += xv.z * wv1;
            acc[3][0] += xv.w * wv0;  acc[3][1] += xv.w * wv1;
        }

        #pragma unroll
        for (int m = 0; m < 4; m++) {
            int p = p0 + pq + m;
            if (p < PP) {
                g_xw1[p * JP + l] = acc[m][0];
                g_xw1[p * JP + j1] = v1 ? acc[m][1] : 0.f;
            }
        }
    }
}

// ============================================================
// k_main (R10 structure + 2-deep a-prefetch): 8 threads per
// (b,p); member q owns j in [8q,8q+8). grid = (160, 2 chunks, 2 b).
// a[s-2] is issued while a[s] is consumed -> the ~234cyc L2 hit
// is covered by two iterations of FMA/SHFL work.
// relu-dot: scalar fmaxf/fmaf (no packed f32 max exists in PTX).
// ============================================================
__global__ void __launch_bounds__(256)
k_main(const int* __restrict__ tgt, const float* __restrict__ cosX,
       const float* __restrict__ W2, const float* __restrict__ b2,
       float* __restrict__ out)
{
    __shared__ float Gs[TT * JP];   // 12.8 KB
    __shared__ int   tg[TT];
    int tid = threadIdx.x;
    int b = blockIdx.z;

    {
        const float4* src = (const float4*)(g_G + b * TT * JP);
        float4* dst = (float4*)Gs;
        for (int i = tid; i < TT * JP / 4; i += 256) dst[i] = src[i];
        if (tid < TT) tg[tid] = tgt[b * TT + tid];
    }
    __syncthreads();

    int p = blockIdx.x * 32 + (tid >> 3);
    if (p >= PP) return;
    int q = tid & 7;
    int jb = q * 8;
    int ch = blockIdx.y;
    const int s_lo = ch * SCH;
    const int s_hi = s_lo + SCH - 1;

    // packed accumulators (8 j), initialized from XW1 row
    ull ac0, ac1, ac2, ac3;
    {
        const ulonglong2* x2 = (const ulonglong2*)(g_xw1 + p * JP + jb);
        ulonglong2 xa = x2[0], xb = x2[1];
        ac0 = xa.x; ac1 = xa.y; ac2 = xb.x; ac3 = xb.y;
    }
    float w2r[8];
    #pragma unroll
    for (int m = 0; m < 8; m++) {
        int j = jb + m;
        w2r[m] = (j < JJ) ? W2[j] : 0.f;
    }
    float bias2 = b2[0];

    // -------- phase A (chunk 0 only): tail t = 49..25, no output --------
    if (ch == 0) {
        float aq0 = __ldg(&cosX[(size_t)tg[TT - 1] * PP + p]);
        float aq1 = __ldg(&cosX[(size_t)tg[TT - 2] * PP + p]);
        #pragma unroll 5
        for (int t = TT - 1; t > s_hi; t--) {
            float a = aq0;
            aq0 = aq1;
            aq1 = (t - 2 >= 0) ? __ldg(&cosX[(size_t)tg[t - 2] * PP + p]) : 0.f;

            ull ab = pk2(a, a);
            const ulonglong2* g2 = (const ulonglong2*)(Gs + t * JP + jb);
            ulonglong2 ga = g2[0], gb = g2[1];
            ac0 = fma2(ga.x, ab, ac0);
            ac1 = fma2(ga.y, ab, ac1);
            ac2 = fma2(gb.x, ab, ac2);
            ac3 = fma2(gb.y, ab, ac3);
        }
        // pipeline holds a[s_hi] (aq0), a[s_hi-1] (aq1)
        #pragma unroll 5
        for (int s = s_hi; s >= s_lo; s--) {
            float a = aq0;
            aq0 = aq1;
            aq1 = (s - 2 >= s_lo) ? __ldg(&cosX[(size_t)tg[s - 2] * PP + p]) : 0.f;

            ull ab = pk2(a, a);
            const ulonglong2* g2 = (const ulonglong2*)(Gs + s * JP + jb);
            ulonglong2 ga = g2[0], gb = g2[1];
            ac0 = fma2(ga.x, ab, ac0);
            ac1 = fma2(ga.y, ab, ac1);
            ac2 = fma2(gb.x, ab, ac2);
            ac3 = fma2(gb.y, ab, ac3);

            float f0, f1, f2, f3, f4, f5, f6, f7;
            upk2(f0, f1, ac0); upk2(f2, f3, ac1);
            upk2(f4, f5, ac2); upk2(f6, f7, ac3);

            float part = fmaxf(f0, 0.f) * w2r[0];
            part = fmaf(fmaxf(f1, 0.f), w2r[1], part);
            part = fmaf(fmaxf(f2, 0.f), w2r[2], part);
            part = fmaf(fmaxf(f3, 0.f), w2r[3], part);
            part = fmaf(fmaxf(f4, 0.f), w2r[4], part);
            part = fmaf(fmaxf(f5, 0.f), w2r[5], part);
            part = fmaf(fmaxf(f6, 0.f), w2r[6], part);
            part = fmaf(fmaxf(f7, 0.f), w2r[7], part);

            part += __shfl_xor_sync(0xffffffffu, part, 1);
            part += __shfl_xor_sync(0xffffffffu, part, 2);
            part += __shfl_xor_sync(0xffffffffu, part, 4);
            if (q == 0)
                out[(b * TT + s) * PP + p] = part + bias2;
        }
    } else {
        // -------- chunk 1: s = 49..25, output every iter --------
        float aq0 = __ldg(&cosX[(size_t)tg[s_hi] * PP + p]);
        float aq1 = __ldg(&cosX[(size_t)tg[s_hi - 1] * PP + p]);
        #pragma unroll 5
        for (int s = s_hi; s >= s_lo; s--) {
            float a = aq0;
            aq0 = aq1;
            aq1 = (s - 2 >= s_lo) ? __ldg(&cosX[(size_t)tg[s - 2] * PP + p]) : 0.f;

            ull ab = pk2(a, a);
            const ulonglong2* g2 = (const ulonglong2*)(Gs + s * JP + jb);
            ulonglong2 ga = g2[0], gb = g2[1];
            ac0 = fma2(ga.x, ab, ac0);
            ac1 = fma2(ga.y, ab, ac1);
            ac2 = fma2(gb.x, ab, ac2);
            ac3 = fma2(gb.y, ab, ac3);

            float f0, f1, f2, f3, f4, f5, f6, f7;
            upk2(f0, f1, ac0); upk2(f2, f3, ac1);
            upk2(f4, f5, ac2); upk2(f6, f7, ac3);

            float part = fmaxf(f0, 0.f) * w2r[0];
            part = fmaf(fmaxf(f1, 0.f), w2r[1], part);
            part = fmaf(fmaxf(f2, 0.f), w2r[2], part);
            part = fmaf(fmaxf(f3, 0.f), w2r[3], part);
            part = fmaf(fmaxf(f4, 0.f), w2r[4], part);
            part = fmaf(fmaxf(f5, 0.f), w2r[5], part);
            part = fmaf(fmaxf(f6, 0.f), w2r[6], part);
            part = fmaf(fmaxf(f7, 0.f), w2r[7], part);

            part += __shfl_xor_sync(0xffffffffu, part, 1);
            part += __shfl_xor_sync(0xffffffffu, part, 2);
            part += __shfl_xor_sync(0xffffffffu, part, 4);
            if (q == 0)
                out[(b * TT + s) * PP + p] = part + bias2;
        }
    }
}

// ============================================================
// Launcher
// ============================================================
extern "C" void kernel_launch(void* const* d_in, const int* in_sizes, int n_in,
                              void* d_out, int out_size)
{
    const int   *tgt = nullptr, *cor = nullptr;
    const float *X = nullptr, *cosX = nullptr, *emb2 = nullptr, *Wk = nullptr;
    const float *Wr = nullptr, *bl = nullptr, *W1 = nullptr, *b1 = nullptr;
    const float *W2 = nullptr, *b2 = nullptr;

    int cnt1 = 0;
    for (int i = 0; i < n_in; i++) if (in_sizes[i] == 1) cnt1++;
    int seen1 = 0;

    for (int i = 0; i < n_in; i++) {
        int sz = in_sizes[i];
        const void* ptr = d_in[i];
        if (sz == BB * TT) {
            if (!tgt) tgt = (const int*)ptr; else cor = (const int*)ptr;
        } else if (sz == PP * PP)   cosX = (const float*)ptr;
        else if (sz == PP * D2)     X    = (const float*)ptr;
        else if (sz == D4 * D4)     Wk   = (const float*)ptr;
        else if (sz == UU * D4)     Wr   = (const float*)ptr;
        else if (sz == 2 * D4)      emb2 = (const float*)ptr;
        else if (sz == D4)          bl   = (const float*)ptr;
        else if (sz == 3 * UU * JJ) W1   = (const float*)ptr;
        else if (sz == JJ) {
            if (!b1) b1 = (const float*)ptr; else W2 = (const float*)ptr;
        } else if (sz == 1) {
            seen1++;
            if (seen1 == cnt1) b2 = (const float*)ptr;
        }
    }

    // 1) zin (400 blocks, MLP-16) + cosX prefetch (R10 exact)
    k_pre<<<NBLK_PRE, 256>>>(tgt, cor, X, emb2, Wk, bl, cosX);
    // 2) LSTM (FFMA2) + XW1 GEMM (R10 exact)
    k_mid<<<NBLK_MID, 256>>>(X, Wr, W1, b1);
    // 3) suffix-sum + MLP; 2-deep a-prefetch, scalar relu-dot
    k_main<<<dim3(160, 2, 2), 256>>>(tgt, cosX, W2, b2, (float*)d_out);
}

// round 17
// speedup vs baseline: 1.3714x; 1.0870x over previous
#include <cuda_runtime.h>

#define BB 2
#define TT 50
#define UU 64
#define PP 5111
#define D4 256   // 4U
#define D2 128   // 2U
#define JJ 50    // MLP hidden
#define JP 64    // padded j-stride
#define SCH 25   // s per chunk (2 chunks)

// k_pre role layout (R10-proven): zin 400 blocks + prefetch 100
#define NZIN 400                   // 100 bt x 4 d-chunks
#define BID_PF NZIN                // 400..499
#define NPF 100                    // one cosX row per block
#define NBLK_PRE (NZIN + NPF)      // 500

// k_mid role layout (R10-proven): lstm + xw1
#define NXW 160
#define NBLK_MID (2 + NXW)         // 162

#define XP  36               // padded p-stride in transposed x tile
#define NLD 20               // ceil(5111/256)

// ---- scratch (device globals; no allocation allowed) ----
__device__ float g_zin[BB * TT * D4];    // xt@Wk + bl
__device__ float g_G  [BB * TT * JP];    // ht @ W1[:64], padded, zeros j>=50
__device__ float g_xw1[(PP + 128) * JP]; // X @ W1[64:192] + b1, padded
__device__ float g_sink[NPF * 256];      // prefetch sink (deterministic)

typedef unsigned long long ull;

__device__ __forceinline__ float fast_tanh(float x) {
    float r;
    asm("tanh.approx.f32 %0, %1;" : "=f"(r) : "f"(x));
    return r;
}
__device__ __forceinline__ float fast_sigmoid(float x) {
    return fmaf(fast_tanh(0.5f * x), 0.5f, 0.5f);
}
__device__ __forceinline__ ull pk2(float lo, float hi) {
    ull r; asm("mov.b64 %0, {%1, %2};" : "=l"(r) : "f"(lo), "f"(hi)); return r;
}
__device__ __forceinline__ void upk2(float& lo, float& hi, ull v) {
    asm("mov.b64 {%0, %1}, %2;" : "=f"(lo), "=f"(hi) : "l"(v));
}
__device__ __forceinline__ ull fma2(ull a, ull b, ull c) {
    ull d; asm("fma.rn.f32x2 %0, %1, %2, %3;" : "=l"(d) : "l"(a), "l"(b), "l"(c)); return d;
}

// ============================================================
// k_pre (EXACT R10): zin + cosX prefetch.
//   bid [0,400)   : zin (bt = bid>>2, d-chunk = bid&3), MLP-16
//   bid [400,500) : cosX L2 prefetch, 1 row per block, MLP-20
// ============================================================
__global__ void __launch_bounds__(256)
k_pre(const int* __restrict__ tgt, const int* __restrict__ cor,
      const float* __restrict__ X, const float* __restrict__ emb2,
      const float* __restrict__ Wk, const float* __restrict__ bl,
      const float* __restrict__ cosX)
{
    __shared__ float sbuf[512];    // zin: xs[256] + zp[256]
    int tid = threadIdx.x;
    int bid = blockIdx.x;

    if (bid < NZIN) {
        float* xs = sbuf;            // [D4]
        float* zp = sbuf + D4;       // partials (ks 1..3)
        int bt = bid >> 2;
        int ch = bid & 3;
        int dl = tid & 63;
        int ks = tid >> 6;           // 0..3 k-split
        int d  = ch * 64 + dl;

        {
            int tg = tgt[bt];
            int cr = cor[bt];
            xs[tid] = X[tg * D2 + (tid & (D2 - 1))] * emb2[cr * D4 + tid];
        }
        __syncthreads();

        int k0 = ks * 64;
        float acc = 0.f;
        #pragma unroll
        for (int kk = 0; kk < 64; kk += 16) {
            float w[16];
            #pragma unroll
            for (int i = 0; i < 16; i++)
                w[i] = Wk[(k0 + kk + i) * D4 + d];   // 16 LDG in flight
            #pragma unroll
            for (int i = 0; i < 16; i++)
                acc += xs[k0 + kk + i] * w[i];
        }
        if (ks != 0) zp[ks * 64 + dl] = acc;
        __syncthreads();
        if (ks == 0)
            g_zin[bt * D4 + d] = acc + zp[64 + dl] + zp[128 + dl] + zp[192 + dl] + bl[d];
    } else {
        int pb = bid - BID_PF;               // 0..99
        const float* row = cosX + (size_t)tgt[pb] * PP;
        float v[NLD];
        #pragma unroll
        for (int i = 0; i < NLD; i++) {
            int idx = tid + i * 256;
            v[i] = (idx < PP) ? __ldg(row + idx) : 0.f;   // MLP = 20
        }
        float s = 0.f;
        #pragma unroll
        for (int i = 0; i < NLD; i++) s += v[i];
        g_sink[pb * 256 + tid] = s;          // deterministic, prevents DCE
    }
}

// ============================================================
// k_mid (EXACT R10): LSTM (blocks 0-1, FFMA2) + XW1 (2..161).
// ============================================================
__global__ void __launch_bounds__(256)
k_mid(const float* __restrict__ X,  const float* __restrict__ Wr,
      const float* __restrict__ W1, const float* __restrict__ b1)
{
    __shared__ float sbuf[6720];   // lstm: 6720 floats; xw1 uses 4608
    int tid = threadIdx.x;
    int bid = blockIdx.x;

    if (bid < 2) {
        // ---------------- LSTM role (FFMA2 dot) ----------------
        int b = bid;
        int d = tid;                        // 0..255

        ull wrp[UU / 2];
        #pragma unroll
        for (int i = 0; i < UU / 2; i++)
            wrp[i] = pk2(Wr[(2 * i) * D4 + d], Wr[(2 * i + 1) * D4 + d]);

        float* hts = sbuf;                   // [(TT+1)*UU] = 3264
        float* zs  = sbuf + (TT + 1) * UU;   // [D4]
        float* w1s = zs + D4;                // [UU*JJ] = 3200

        for (int i = tid; i < UU * JJ; i += 256) w1s[i] = W1[i];

        float creg = 0.f;
        if (d < UU) hts[d] = 0.f;

        float znext = g_zin[(b * TT) * D4 + d];
        __syncthreads();

        const ull z2 = pk2(0.f, 0.f);

        for (int t = 0; t < TT; t++) {
            float z = znext;
            if (t < TT - 1)
                znext = g_zin[(b * TT + t + 1) * D4 + d];

            const ull* h2 = (const ull*)(hts + t * UU);
            ull a0 = z2, a1 = z2, a2 = z2, a3 = z2;
            #pragma unroll
            for (int i = 0; i < UU / 2; i += 4) {
                a0 = fma2(h2[i],     wrp[i],     a0);
                a1 = fma2(h2[i + 1], wrp[i + 1], a1);
                a2 = fma2(h2[i + 2], wrp[i + 2], a2);
                a3 = fma2(h2[i + 3], wrp[i + 3], a3);
            }
            float f0, f1, f2, f3, f4, f5, f6, f7;
            upk2(f0, f1, a0); upk2(f2, f3, a1);
            upk2(f4, f5, a2); upk2(f6, f7, a3);
            zs[d] = z + ((f0 + f1) + (f2 + f3)) + ((f4 + f5) + (f6 + f7));
            __syncthreads();
            if (d < UU) {
                float gi = fast_sigmoid(zs[d]);
                float gf = fast_sigmoid(zs[UU + d]);
                float gg = fast_tanh(zs[2 * UU + d]);
                float go = fast_sigmoid(zs[3 * UU + d]);
                creg = gf * creg + gi * gg;
                hts[(t + 1) * UU + d] = go * fast_tanh(creg);
            }
            __syncthreads();
        }

        // fused: G[b,t,j] = sum_u h_t[u]*W1[u,j]; padded stride JP
        for (int idx = tid; idx < TT * JP; idx += 256) {
            int t = idx >> 6;
            int j = idx & (JP - 1);
            float v = 0.f;
            if (j < JJ) {
                const float* h = hts + (t + 1) * UU;
                float s0 = 0.f, s1 = 0.f;
                #pragma unroll
                for (int u = 0; u < UU; u += 2) {
                    s0 += h[u]     * w1s[u * JJ + j];
                    s1 += h[u + 1] * w1s[(u + 1) * JJ + j];
                }
                v = s0 + s1;
            }
            g_G[(b * TT + t) * JP + j] = v;
        }
    } else {
        // ---------------- XW1 role ----------------
        float* xsmT = sbuf;                  // [D2][XP] = 4608
        int p0 = (bid - 2) * 32;
        for (int i = tid; i < 32 * D2; i += 256) {
            int pl = i >> 7;
            int k  = i & (D2 - 1);
            int p  = p0 + pl;
            xsmT[k * XP + pl] = (p < PP) ? X[p * D2 + k] : 0.f;
        }
        __syncthreads();

        int w = tid >> 5;
        int l = tid & 31;
        int j1 = l + 32;
        bool v1 = (j1 < JJ);
        int pq = w * 4;
        const float* W1b = W1 + UU * JJ;

        float acc[4][2];
        float b0 = b1[l];
        float b1v = v1 ? b1[j1] : 0.f;
        #pragma unroll
        for (int m = 0; m < 4; m++) { acc[m][0] = b0; acc[m][1] = b1v; }

        #pragma unroll 4
        for (int k = 0; k < D2; k++) {
            float4 xv = *(const float4*)(xsmT + k * XP + pq);
            float wv0 = __ldg(W1b + k * JJ + l);
            float wv1 = v1 ? __ldg(W1b + k * JJ + j1) : 0.f;
            acc[0][0] += xv.x * wv0;  acc[0][1] += xv.x * wv1;
            acc[1][0] += xv.y * wv0;  acc[1][1] += xv.y * wv1;
            acc[2][0] += xv.z * wv0;  acc[2][1] += xv.z * wv1;
            acc[3][0] += xv.w * wv0;  acc[3][1] += xv.w * wv1;
        }

        #pragma unroll
        for (int m = 0; m < 4; m++) {
            int p = p0 + pq + m;
            if (p < PP) {
                g_xw1[p * JP + l] = acc[m][0];
                g_xw1[p * JP + j1] = v1 ? acc[m][1] : 0.f;
            }
        }
    }
}

// ============================================================
// k_main (RESTRUCTURED): ONE thread per (b,p), all 50 j in
// registers (25 packed f32x2 accumulators). No SHFL reduce, no
// cross-thread redundancy; a-loads and out-stores fully coalesced.
// grid = (40 p-blocks x 128, 2 s-chunks, 2 b).
// ============================================================
__global__ void __launch_bounds__(128)
k_main(const int* __restrict__ tgt, const float* __restrict__ cosX,
       const float* __restrict__ W2, const float* __restrict__ b2,
       float* __restrict__ out)
{
    __shared__ float Gs[TT * JP];   // 12.8 KB
    __shared__ int   tg[TT];
    int tid = threadIdx.x;
    int b = blockIdx.z;

    {
        const float4* src = (const float4*)(g_G + b * TT * JP);
        float4* dst = (float4*)Gs;
        for (int i = tid; i < TT * JP / 4; i += 128) dst[i] = src[i];
        if (tid < TT) tg[tid] = tgt[b * TT + tid];
    }
    __syncthreads();

    int p = blockIdx.x * 128 + tid;
    bool valid = (p < PP);
    int pc = valid ? p : (PP - 1);       // clamp for safe loads
    int ch = blockIdx.y;
    const int s_lo = ch * SCH;
    const int s_hi = s_lo + SCH - 1;

    // 25 packed accumulators = 50 j, init from XW1 row (pad rows safe)
    ull ac[25];
    {
        const ull* x2 = (const ull*)(g_xw1 + (size_t)pc * JP);
        #pragma unroll
        for (int m = 0; m < 25; m++) ac[m] = x2[m];
    }
    // W2 broadcast into registers (one-time, L1 hits)
    float w2r[50];
    #pragma unroll
    for (int m = 0; m < 50; m++) w2r[m] = __ldg(W2 + m);
    float bias2 = b2[0];

    // 2-deep a prefetch pipeline, starting at t = 49
    float aq0 = __ldg(&cosX[(size_t)tg[TT - 1] * PP + pc]);
    float aq1 = __ldg(&cosX[(size_t)tg[TT - 2] * PP + pc]);

    // -------- phase A: light accumulate t = 49 .. s_hi+1 --------
    #pragma unroll 1
    for (int t = TT - 1; t > s_hi; t--) {
        float a = aq0;
        aq0 = aq1;
        aq1 = (t - 2 >= s_lo) ? __ldg(&cosX[(size_t)tg[t - 2] * PP + pc]) : 0.f;

        ull ab = pk2(a, a);
        const ulonglong2* g2 = (const ulonglong2*)(Gs + t * JP);
        #pragma unroll
        for (int m = 0; m < 12; m++) {
            ulonglong2 gg = g2[m];
            ac[2 * m]     = fma2(gg.x, ab, ac[2 * m]);
            ac[2 * m + 1] = fma2(gg.y, ab, ac[2 * m + 1]);
        }
        ac[24] = fma2(((const ull*)(Gs + t * JP))[24], ab, ac[24]);
    }

    // -------- phase B: s = s_hi .. s_lo, output every iter --------
    #pragma unroll 1
    for (int s = s_hi; s >= s_lo; s--) {
        float a = aq0;
        aq0 = aq1;
        aq1 = (s - 2 >= s_lo) ? __ldg(&cosX[(size_t)tg[s - 2] * PP + pc]) : 0.f;

        ull ab = pk2(a, a);
        const ulonglong2* g2 = (const ulonglong2*)(Gs + s * JP);
        #pragma unroll
        for (int m = 0; m < 12; m++) {
            ulonglong2 gg = g2[m];
            ac[2 * m]     = fma2(gg.x, ab, ac[2 * m]);
            ac[2 * m + 1] = fma2(gg.y, ab, ac[2 * m + 1]);
        }
        ac[24] = fma2(((const ull*)(Gs + s * JP))[24], ab, ac[24]);

        // relu-dot over 50 j, 4 independent partial chains
        float p0 = 0.f, p1 = 0.f, p2 = 0.f, p3 = 0.f;
        #pragma unroll
        for (int m = 0; m < 24; m += 4) {
            float lo, hi;
            upk2(lo, hi, ac[m]);
            p0 = fmaf(fmaxf(lo, 0.f), w2r[2 * m],     p0);
            p1 = fmaf(fmaxf(hi, 0.f), w2r[2 * m + 1], p1);
            upk2(lo, hi, ac[m + 1]);
            p2 = fmaf(fmaxf(lo, 0.f), w2r[2 * m + 2], p2);
            p3 = fmaf(fmaxf(hi, 0.f), w2r[2 * m + 3], p3);
            upk2(lo, hi, ac[m + 2]);
            p0 = fmaf(fmaxf(lo, 0.f), w2r[2 * m + 4], p0);
            p1 = fmaf(fmaxf(hi, 0.f), w2r[2 * m + 5], p1);
            upk2(lo, hi, ac[m + 3]);
            p2 = fmaf(fmaxf(lo, 0.f), w2r[2 * m + 6], p2);
            p3 = fmaf(fmaxf(hi, 0.f), w2r[2 * m + 7], p3);
        }
        {
            float lo, hi;
            upk2(lo, hi, ac[24]);
            p0 = fmaf(fmaxf(lo, 0.f), w2r[48], p0);
            p1 = fmaf(fmaxf(hi, 0.f), w2r[49], p1);
        }
        float part = (p0 + p1) + (p2 + p3);

        if (valid)
            out[(b * TT + s) * PP + p] = part + bias2;
    }
}

// ============================================================
// Launcher
// ============================================================
extern "C" void kernel_launch(void* const* d_in, const int* in_sizes, int n_in,
                              void* d_out, int out_size)
{
    const int   *tgt = nullptr, *cor = nullptr;
    const float *X = nullptr, *cosX = nullptr, *emb2 = nullptr, *Wk = nullptr;
    const float *Wr = nullptr, *bl = nullptr, *W1 = nullptr, *b1 = nullptr;
    const float *W2 = nullptr, *b2 = nullptr;

    int cnt1 = 0;
    for (int i = 0; i < n_in; i++) if (in_sizes[i] == 1) cnt1++;
    int seen1 = 0;

    for (int i = 0; i < n_in; i++) {
        int sz = in_sizes[i];
        const void* ptr = d_in[i];
        if (sz == BB * TT) {
            if (!tgt) tgt = (const int*)ptr; else cor = (const int*)ptr;
        } else if (sz == PP * PP)   cosX = (const float*)ptr;
        else if (sz == PP * D2)     X    = (const float*)ptr;
        else if (sz == D4 * D4)     Wk   = (const float*)ptr;
        else if (sz == UU * D4)     Wr   = (const float*)ptr;
        else if (sz == 2 * D4)      emb2 = (const float*)ptr;
        else if (sz == D4)          bl   = (const float*)ptr;
        else if (sz == 3 * UU * JJ) W1   = (const float*)ptr;
        else if (sz == JJ) {
            if (!b1) b1 = (const float*)ptr; else W2 = (const float*)ptr;
        } else if (sz == 1) {
            seen1++;
            if (seen1 == cnt1) b2 = (const float*)ptr;
        }
    }

    // 1) zin (400 blocks, MLP-16) + cosX prefetch (R10 exact)
    k_pre<<<NBLK_PRE, 256>>>(tgt, cor, X, emb2, Wk, bl, cosX);
    // 2) LSTM (FFMA2) + XW1 GEMM (R10 exact)
    k_mid<<<NBLK_MID, 256>>>(X, Wr, W1, b1);
    // 3) suffix-sum + MLP; 1 thread per (b,p), 50 j in regs, no reduce
    k_main<<<dim3((PP + 127) / 128, 2, 2), 128>>>(tgt, cosX, W2, b2, (float*)d_out);
}